// round 1
// baseline (speedup 1.0000x reference)
#include <cuda_runtime.h>

// Problem constants
#define BB   32
#define NN   1024
#define GG   8
#define HH   128
#define KOUT 128

// Scratch (static device globals: legal, no runtime allocation)
__device__ float g_H0[BB * NN * HH];   // 16.8 MB
__device__ float g_H1[BB * NN * HH];   // 16.8 MB

// sqrt without MUFU: magic rsqrt seed + 3 Newton steps on the FMA pipe.
// rel err < 1e-7 after 3 iters; fast_sqrt(0) == 0 (0 * finite = 0).
__device__ __forceinline__ float fast_sqrt(float v) {
    float xh = 0.5f * v;
    int i = __float_as_int(v);
    i = 0x5f3759df - (i >> 1);
    float y = __int_as_float(i);
    y = y * (1.5f - xh * y * y);
    y = y * (1.5f - xh * y * y);
    y = y * (1.5f - xh * y * y);
    return v * y;
}

__device__ __forceinline__ float leaky(float v) {
    return v > 0.0f ? v : 0.01f * v;
}

// ---------------------------------------------------------------------------
// Kernel 0: zero the output (harness poisons d_out)
// ---------------------------------------------------------------------------
__global__ void k_zero(float* __restrict__ out) {
    out[blockIdx.x * 1024 + threadIdx.x] = 0.0f;
}

// ---------------------------------------------------------------------------
// Kernel 1: fused scalars + layer 0.
// H0[b,i,h] = leaky( b0[h] + sum_g u[b,g]W0[g,h] + norm_i W0[8,h]
//                    + sum_j sqrt(x_i . x_j) W0[9+j,h] )
// Tile: 64 rows (i) x 128 cols (h), K-tiles of 32 (j). 256 threads,
// each owns an 8x4 register accumulator. A-tile (sqrt of gram) generated
// in smem each K-step — dots tensor never touches global memory.
// ---------------------------------------------------------------------------
__global__ __launch_bounds__(256) void k_layer0(
    const float* __restrict__ x, const float* __restrict__ u,
    const float* __restrict__ W0, const float* __restrict__ b0)
{
    const int b   = blockIdx.x >> 4;
    const int i0  = (blockIdx.x & 15) * 64;
    const int tid = threadIdx.x;
    const int ty  = tid >> 5;   // warp id 0..7 -> row group
    const int tx  = tid & 31;   // lane        -> col group

    __shared__ float As[64][33];     // A tile [i][k], padded (conflict-free gen writes)
    __shared__ float Bs[32][128];    // W0 dots-rows tile [k][h]
    __shared__ float xi[64][3];
    __shared__ float cu[128];        // b0 + u @ W0[0:8]
    __shared__ float w0n[128];       // W0[8,:]
    __shared__ float nrm[64];

    if (tid < 192) ((float*)xi)[tid] = x[(b * NN + i0) * 3 + tid];
    if (tid < 128) {
        float s = b0[tid];
        #pragma unroll
        for (int g = 0; g < GG; g++) s += u[b * GG + g] * W0[g * HH + tid];
        cu[tid]  = s;
        w0n[tid] = W0[8 * HH + tid];
    }
    __syncthreads();
    if (tid < 64) {
        float a = xi[tid][0], bb = xi[tid][1], c = xi[tid][2];
        nrm[tid] = fast_sqrt(a * a + bb * bb + c * c);
    }
    __syncthreads();

    float acc[8][4];
    {
        float cuv[4], wnv[4];
        #pragma unroll
        for (int c = 0; c < 4; c++) { cuv[c] = cu[tx * 4 + c]; wnv[c] = w0n[tx * 4 + c]; }
        #pragma unroll
        for (int r = 0; r < 8; r++) {
            float nv = nrm[ty * 8 + r];
            #pragma unroll
            for (int c = 0; c < 4; c++) acc[r][c] = fmaf(nv, wnv[c], cuv[c]);
        }
    }

    const int ac  = tid >> 3;        // A column (j within tile) 0..31
    const int ar0 = (tid & 7) * 8;   // A row base

    for (int kt = 0; kt < 32; kt++) {
        const int j0 = kt * 32;
        __syncthreads();   // previous As/Bs fully consumed

        // Bs <- W0 rows [9+j0, 9+j0+32): 4096 contiguous floats
        {
            const float4* src = (const float4*)(W0 + (9 + j0) * HH);
            float4* dst = (float4*)&Bs[0][0];
            #pragma unroll
            for (int m = 0; m < 4; m++) dst[tid + m * 256] = src[tid + m * 256];
        }
        // Generate A tile: As[i][k] = sqrt(x_i . x_{j0+k})
        {
            const float* xjp = x + (b * NN + j0 + ac) * 3;
            float xj0 = __ldg(xjp), xj1 = __ldg(xjp + 1), xj2 = __ldg(xjp + 2);
            #pragma unroll
            for (int rr = 0; rr < 8; rr++) {
                int r = ar0 + rr;
                float d = xi[r][0] * xj0 + xi[r][1] * xj1 + xi[r][2] * xj2;
                As[r][ac] = fast_sqrt(d);
            }
        }
        __syncthreads();

        #pragma unroll 8
        for (int k = 0; k < 32; k++) {
            float4 bq = *(const float4*)&Bs[k][tx * 4];
            float bv[4] = {bq.x, bq.y, bq.z, bq.w};
            #pragma unroll
            for (int r = 0; r < 8; r++) {
                float av = As[ty * 8 + r][k];   // warp-uniform broadcast
                #pragma unroll
                for (int c = 0; c < 4; c++) acc[r][c] = fmaf(av, bv[c], acc[r][c]);
            }
        }
    }

    float* dst = g_H0 + (size_t)(b * NN + i0) * HH;
    #pragma unroll
    for (int r = 0; r < 8; r++) {
        float4 v;
        v.x = leaky(acc[r][0]); v.y = leaky(acc[r][1]);
        v.z = leaky(acc[r][2]); v.w = leaky(acc[r][3]);
        *(float4*)&dst[(ty * 8 + r) * HH + tx * 4] = v;
    }
}

// ---------------------------------------------------------------------------
// Kernel 2: generic [64 x 128] x [128 x 128] dense layer (leaky optional)
// ---------------------------------------------------------------------------
template<bool LEAKY>
__global__ __launch_bounds__(256) void k_dense(
    const float* __restrict__ A, const float* __restrict__ W,
    const float* __restrict__ bias, float* __restrict__ O)
{
    const int gi0 = blockIdx.x * 64;
    const int tid = threadIdx.x;
    const int ty  = tid >> 5;
    const int tx  = tid & 31;

    __shared__ float As[64][32];
    __shared__ float Ws[32][128];

    float acc[8][4];
    #pragma unroll
    for (int r = 0; r < 8; r++)
        #pragma unroll
        for (int c = 0; c < 4; c++) acc[r][c] = __ldg(bias + tx * 4 + c);

    for (int kt = 0; kt < 4; kt++) {
        __syncthreads();
        // A tile: rows gi0..gi0+63, cols kt*32..+31
        #pragma unroll
        for (int m = 0; m < 2; m++) {
            int idx = tid + m * 256;           // float4 index 0..511
            int il = idx >> 3, kq = idx & 7;
            *(float4*)&As[il][kq * 4] =
                *(const float4*)&A[(size_t)(gi0 + il) * HH + kt * 32 + kq * 4];
        }
        // W tile: rows kt*32..+31 contiguous
        {
            const float4* src = (const float4*)(W + kt * 32 * HH);
            float4* dst = (float4*)&Ws[0][0];
            #pragma unroll
            for (int m = 0; m < 4; m++) dst[tid + m * 256] = src[tid + m * 256];
        }
        __syncthreads();

        #pragma unroll 8
        for (int k = 0; k < 32; k++) {
            float4 bq = *(const float4*)&Ws[k][tx * 4];
            float bv[4] = {bq.x, bq.y, bq.z, bq.w};
            #pragma unroll
            for (int r = 0; r < 8; r++) {
                float av = As[ty * 8 + r][k];
                #pragma unroll
                for (int c = 0; c < 4; c++) acc[r][c] = fmaf(av, bv[c], acc[r][c]);
            }
        }
    }

    float* dst = O + (size_t)gi0 * HH;
    #pragma unroll
    for (int r = 0; r < 8; r++) {
        float4 v;
        v.x = acc[r][0]; v.y = acc[r][1]; v.z = acc[r][2]; v.w = acc[r][3];
        if (LEAKY) { v.x = leaky(v.x); v.y = leaky(v.y); v.z = leaky(v.z); v.w = leaky(v.w); }
        *(float4*)&dst[(ty * 8 + r) * HH + tx * 4] = v;
    }
}

// ---------------------------------------------------------------------------
// Kernel 3: layer 2 (no activation) fused with the output contraction:
// out[b,o,d] += sum_i fk[b,i,o] * x[b,i,d] / N    (fp32 global atomics)
// ---------------------------------------------------------------------------
__global__ __launch_bounds__(256) void k_last(
    const float* __restrict__ A, const float* __restrict__ W,
    const float* __restrict__ bias, const float* __restrict__ x,
    float* __restrict__ out)
{
    const int gi0 = blockIdx.x * 64;
    const int b   = gi0 >> 10;
    const int tid = threadIdx.x;
    const int ty  = tid >> 5;
    const int tx  = tid & 31;

    __shared__ float As[64][32];
    __shared__ float Ws[32][128];

    float acc[8][4];
    #pragma unroll
    for (int r = 0; r < 8; r++)
        #pragma unroll
        for (int c = 0; c < 4; c++) acc[r][c] = __ldg(bias + tx * 4 + c);

    for (int kt = 0; kt < 4; kt++) {
        __syncthreads();
        #pragma unroll
        for (int m = 0; m < 2; m++) {
            int idx = tid + m * 256;
            int il = idx >> 3, kq = idx & 7;
            *(float4*)&As[il][kq * 4] =
                *(const float4*)&A[(size_t)(gi0 + il) * HH + kt * 32 + kq * 4];
        }
        {
            const float4* src = (const float4*)(W + kt * 32 * HH);
            float4* dst = (float4*)&Ws[0][0];
            #pragma unroll
            for (int m = 0; m < 4; m++) dst[tid + m * 256] = src[tid + m * 256];
        }
        __syncthreads();

        #pragma unroll 8
        for (int k = 0; k < 32; k++) {
            float4 bq = *(const float4*)&Ws[k][tx * 4];
            float bv[4] = {bq.x, bq.y, bq.z, bq.w};
            #pragma unroll
            for (int r = 0; r < 8; r++) {
                float av = As[ty * 8 + r][k];
                #pragma unroll
                for (int c = 0; c < 4; c++) acc[r][c] = fmaf(av, bv[c], acc[r][c]);
            }
        }
    }

    // Contraction against x, then atomic accumulate into out[b, o, d]
    float p[4][3];
    #pragma unroll
    for (int c = 0; c < 4; c++)
        #pragma unroll
        for (int d = 0; d < 3; d++) p[c][d] = 0.0f;

    #pragma unroll
    for (int r = 0; r < 8; r++) {
        const float* xp = x + (size_t)(gi0 + ty * 8 + r) * 3;
        float x0 = __ldg(xp), x1 = __ldg(xp + 1), x2 = __ldg(xp + 2);
        #pragma unroll
        for (int c = 0; c < 4; c++) {
            float f = acc[r][c];
            p[c][0] = fmaf(f, x0, p[c][0]);
            p[c][1] = fmaf(f, x1, p[c][1]);
            p[c][2] = fmaf(f, x2, p[c][2]);
        }
    }
    const float inv = 1.0f / (float)NN;
    #pragma unroll
    for (int c = 0; c < 4; c++)
        #pragma unroll
        for (int d = 0; d < 3; d++)
            atomicAdd(out + (size_t)b * KOUT * 3 + (tx * 4 + c) * 3 + d, p[c][d] * inv);
}

// ---------------------------------------------------------------------------
// Launch: zero -> layer0(fused gram) -> layer1 -> layer2+reduce
// ---------------------------------------------------------------------------
extern "C" void kernel_launch(void* const* d_in, const int* in_sizes, int n_in,
                              void* d_out, int out_size) {
    const float* x  = (const float*)d_in[0];
    const float* u  = (const float*)d_in[1];
    const float* W0 = (const float*)d_in[2];
    const float* b0 = (const float*)d_in[3];
    const float* W1 = (const float*)d_in[4];
    const float* b1 = (const float*)d_in[5];
    const float* W2 = (const float*)d_in[6];
    const float* b2 = (const float*)d_in[7];
    float* out = (float*)d_out;

    float *H0, *H1;
    cudaGetSymbolAddress((void**)&H0, g_H0);
    cudaGetSymbolAddress((void**)&H1, g_H1);

    k_zero<<<(BB * KOUT * 3) / 1024, 1024>>>(out);
    k_layer0<<<BB * (NN / 64), 256>>>(x, u, W0, b0);
    k_dense<true><<<BB * (NN / 64), 256>>>(H0, W1, b1, H1);
    k_last<<<BB * (NN / 64), 256>>>(H1, W2, b2, x, out);
}

// round 3
// speedup vs baseline: 2.2228x; 2.2228x over previous
#include <cuda_runtime.h>
#include <cuda_bf16.h>

#define BB 32
#define NN 1024
#define GG 8
#define HH 128

// ---- prepped bf16 hi/lo operand images, ldmatrix-swizzled k64-chunk blocks ----
// block layout: 64 k-rows x 128 n-cols bf16; row stride 256B; 16B-chunk index
// within a row is XOR-swizzled by (k & 7).
__device__ __align__(16) unsigned char gBd_hi[16 * 16384];  // W0 rows 9..1032 (dots)
__device__ __align__(16) unsigned char gBd_lo[16 * 16384];
__device__ __align__(16) unsigned char gW1_hi[2 * 16384];
__device__ __align__(16) unsigned char gW1_lo[2 * 16384];
__device__ __align__(16) unsigned char gW2_hi[2 * 16384];
__device__ __align__(16) unsigned char gW2_lo[2 * 16384];

// ---- smem map (bytes) ----
#define OFF_AH   0        // layer0 A hi (128 x 64 bf16, 128B rows) | later h hi (128 x 128, 256B rows)
#define OFF_AL   16384    // layer0 A lo
#define OFF_BH   32768    // layer0 B hi (k64 chunk)                | later h lo
#define OFF_BL   49152
#define OFF_WH   65536    // layer1/2 W chunk hi
#define OFF_WL   81920
#define OFF_XI   98304    // x rows of this CTA tile, fp32 [128][3]
#define OFF_NRM  99840
#define OFF_CU   100352
#define OFF_W0N  100864
#define OFF_B1S  101376
#define OFF_B2S  101888
#define OFF_OACC 102400   // fp32 [128][3]
#define SMEM_BYTES 103936

// ---------------- helpers ----------------
__device__ __forceinline__ unsigned smem_u32(const void* p) {
    unsigned a;
    asm("{ .reg .u64 t; cvta.to.shared.u64 t, %1; cvt.u32.u64 %0, t; }" : "=r"(a) : "l"(p));
    return a;
}
__device__ __forceinline__ void ldsm_x4(unsigned& r0, unsigned& r1, unsigned& r2, unsigned& r3,
                                        unsigned a) {
    asm volatile("ldmatrix.sync.aligned.m8n8.x4.shared.b16 {%0,%1,%2,%3}, [%4];"
                 : "=r"(r0), "=r"(r1), "=r"(r2), "=r"(r3) : "r"(a));
}
__device__ __forceinline__ void ldsm_x2t(unsigned& r0, unsigned& r1, unsigned a) {
    asm volatile("ldmatrix.sync.aligned.m8n8.x2.trans.shared.b16 {%0,%1}, [%2];"
                 : "=r"(r0), "=r"(r1) : "r"(a));
}
__device__ __forceinline__ void mma16816(float* d, unsigned a0, unsigned a1, unsigned a2,
                                         unsigned a3, unsigned b0, unsigned b1) {
    asm volatile(
        "mma.sync.aligned.m16n8k16.row.col.f32.bf16.bf16.f32 "
        "{%0,%1,%2,%3}, {%4,%5,%6,%7}, {%8,%9}, {%0,%1,%2,%3};"
        : "+f"(d[0]), "+f"(d[1]), "+f"(d[2]), "+f"(d[3])
        : "r"(a0), "r"(a1), "r"(a2), "r"(a3), "r"(b0), "r"(b1));
}
__device__ __forceinline__ float fast_sqrt(float v) {
    float xh = 0.5f * v;
    int i = __float_as_int(v);
    i = 0x5f3759df - (i >> 1);
    float y = __int_as_float(i);
    y = y * (1.5f - xh * y * y);
    y = y * (1.5f - xh * y * y);
    y = y * (1.5f - xh * y * y);
    return v * y;
}
__device__ __forceinline__ float leaky(float v) { return v > 0.0f ? v : 0.01f * v; }

__device__ __forceinline__ unsigned short bf16bits(float v) {
    __nv_bfloat16 h = __float2bfloat16(v);
    return *(unsigned short*)&h;
}
__device__ __forceinline__ float bf16val(unsigned short b) {
    __nv_bfloat16 h = *(__nv_bfloat16*)&b;
    return __bfloat162float(h);
}

// k64 MMA sweep: acc[16][4] += (Ah+Al) x (Bh+Bl) (3-term split).
// RSTRIDE = A row stride in bytes (128 for layer0, 256 for h).
// kOff = A k offset (0 for layer0 per-chunk A, cb2*64 for h).
template<int RSTRIDE>
__device__ __forceinline__ void mma_k64(float (&acc)[16][4], unsigned aH, unsigned aL,
                                        unsigned bH, unsigned bL, int kOff, int w, int lane) {
    const int L = lane;
    const int i = w * 16 + (L & 15);
    #pragma unroll
    for (int ks = 0; ks < 64; ks += 16) {
        const int kc = ((kOff + ks) >> 3) + (L >> 4);
        const unsigned aoff = i * RSTRIDE + ((kc ^ (i & 7)) << 4);
        unsigned ah0, ah1, ah2, ah3, al0, al1, al2, al3;
        ldsm_x4(ah0, ah1, ah2, ah3, aH + aoff);
        ldsm_x4(al0, al1, al2, al3, aL + aoff);
        const int kk = ks + (L & 15);
        const unsigned bbase = kk * 256;
        const int kx = kk & 7;
        #pragma unroll
        for (int nf = 0; nf < 16; nf++) {
            const unsigned boff = bbase + (((nf ^ kx)) << 4);
            unsigned bh0, bh1, bl0, bl1;
            ldsm_x2t(bh0, bh1, bH + boff);
            ldsm_x2t(bl0, bl1, bL + boff);
            mma16816(acc[nf], ah0, ah1, ah2, ah3, bh0, bh1);
            mma16816(acc[nf], ah0, ah1, ah2, ah3, bl0, bl1);
            mma16816(acc[nf], al0, al1, al2, al3, bh0, bh1);
        }
    }
}

// Epilogue: leaky + hi/lo split into h region (256B rows, swizzled), re-init acc with bias.
__device__ __forceinline__ void epi_split(float (&acc)[16][4], unsigned char* dH,
                                          unsigned char* dL, const float* nb, int w, int lane) {
    const int cp = lane & 3, rg = lane >> 2;
    const int r1 = w * 16 + rg, r2 = r1 + 8;
    #pragma unroll
    for (int nf = 0; nf < 16; nf++) {
        const int c = nf * 8 + cp * 2;
        float v0 = leaky(acc[nf][0]), v1 = leaky(acc[nf][1]);
        float v2 = leaky(acc[nf][2]), v3 = leaky(acc[nf][3]);
        unsigned short h0 = bf16bits(v0), h1 = bf16bits(v1);
        unsigned short h2 = bf16bits(v2), h3 = bf16bits(v3);
        unsigned short l0 = bf16bits(v0 - bf16val(h0)), l1 = bf16bits(v1 - bf16val(h1));
        unsigned short l2 = bf16bits(v2 - bf16val(h2)), l3 = bf16bits(v3 - bf16val(h3));
        const unsigned o1 = r1 * 256 + ((((c >> 3) ^ (r1 & 7))) << 4) + (c & 7) * 2;
        const unsigned o2 = r2 * 256 + ((((c >> 3) ^ (r2 & 7))) << 4) + (c & 7) * 2;
        *(unsigned*)(dH + o1) = (unsigned)h0 | ((unsigned)h1 << 16);
        *(unsigned*)(dL + o1) = (unsigned)l0 | ((unsigned)l1 << 16);
        *(unsigned*)(dH + o2) = (unsigned)h2 | ((unsigned)h3 << 16);
        *(unsigned*)(dL + o2) = (unsigned)l2 | ((unsigned)l3 << 16);
        acc[nf][0] = nb[c]; acc[nf][1] = nb[c + 1];
        acc[nf][2] = nb[c]; acc[nf][3] = nb[c + 1];
    }
}

// ---------------------------------------------------------------------------
__global__ void k_zero(float* __restrict__ out) {
    out[blockIdx.x * 1024 + threadIdx.x] = 0.0f;
}

// Prep: split weights into bf16 hi/lo swizzled chunk-block images.
__global__ void k_prep(const float* __restrict__ W0, const float* __restrict__ W1,
                       const float* __restrict__ W2) {
    int idx = blockIdx.x * 256 + threadIdx.x;
    float v; unsigned char *dh, *dl;
    int k, n;
    if (idx < 131072) {                   // dots rows of W0
        k = idx >> 7; n = idx & 127;
        v = W0[(9 + k) * HH + n];
        dh = gBd_hi; dl = gBd_lo;
    } else if (idx < 147456) {            // W1
        int t = idx - 131072;
        k = t >> 7; n = t & 127;
        v = W1[k * HH + n];
        dh = gW1_hi; dl = gW1_lo;
    } else if (idx < 163840) {            // W2
        int t = idx - 147456;
        k = t >> 7; n = t & 127;
        v = W2[k * HH + n];
        dh = gW2_hi; dl = gW2_lo;
    } else return;
    const int cb = k >> 6, kl = k & 63;
    const unsigned off = cb * 16384 + kl * 256 + ((((n >> 3) ^ (kl & 7))) << 4) + (n & 7) * 2;
    unsigned short h = bf16bits(v);
    unsigned short l = bf16bits(v - bf16val(h));
    *(unsigned short*)(dh + off) = h;
    *(unsigned short*)(dl + off) = l;
}

// ---------------------------------------------------------------------------
__global__ void __launch_bounds__(256, 2)
k_main(const float* __restrict__ x, const float* __restrict__ u,
       const float* __restrict__ W0, const float* __restrict__ b0,
       const float* __restrict__ b1, const float* __restrict__ b2,
       float* __restrict__ out)
{
    extern __shared__ __align__(1024) unsigned char smem[];
    const unsigned sb = smem_u32(smem);
    const int tid = threadIdx.x, w = tid >> 5, lane = tid & 31;
    const int b = blockIdx.x >> 3, i0 = (blockIdx.x & 7) * 128;

    float* xi   = (float*)(smem + OFF_XI);
    float* nrm  = (float*)(smem + OFF_NRM);
    float* cu   = (float*)(smem + OFF_CU);
    float* w0n  = (float*)(smem + OFF_W0N);
    float* b1s  = (float*)(smem + OFF_B1S);
    float* b2s  = (float*)(smem + OFF_B2S);
    float* oacc = (float*)(smem + OFF_OACC);

    for (int t = tid; t < 384; t += 256) {
        xi[t] = x[(size_t)(b * NN + i0) * 3 + t];
        oacc[t] = 0.0f;
    }
    if (tid < 128) {
        float s = b0[tid];
        #pragma unroll
        for (int g = 0; g < GG; g++) s += u[b * GG + g] * W0[g * HH + tid];
        cu[tid]  = s;
        w0n[tid] = W0[8 * HH + tid];
        b1s[tid] = b1[tid];
        b2s[tid] = b2[tid];
    }
    __syncthreads();
    if (tid < 128) {
        float a = xi[tid * 3], c = xi[tid * 3 + 1], d = xi[tid * 3 + 2];
        nrm[tid] = fast_sqrt(a * a + c * c + d * d);
    }
    __syncthreads();

    // Accumulators: warp w owns rows [16w, 16w+16), 16 n-fragments of width 8.
    float acc[16][4];
    {
        const int cp = lane & 3, rg = lane >> 2;
        const int r1 = w * 16 + rg, r2 = r1 + 8;
        const float n1 = nrm[r1], n2 = nrm[r2];
        #pragma unroll
        for (int nf = 0; nf < 16; nf++) {
            const int c = nf * 8 + cp * 2;
            acc[nf][0] = cu[c]     + n1 * w0n[c];
            acc[nf][1] = cu[c + 1] + n1 * w0n[c + 1];
            acc[nf][2] = cu[c]     + n2 * w0n[c];
            acc[nf][3] = cu[c + 1] + n2 * w0n[c + 1];
        }
    }

    // ---------------- layer 0 mainloop: 16 chunks of k64 gram columns ----------------
    const int jj = tid & 63, ig = tid >> 6;
    for (int cb = 0; cb < 16; cb++) {
        __syncthreads();
        // stage W0 chunk (hi/lo)
        {
            const float4* srcH = (const float4*)(gBd_hi + cb * 16384);
            const float4* srcL = (const float4*)(gBd_lo + cb * 16384);
            float4* dH = (float4*)(smem + OFF_BH);
            float4* dL = (float4*)(smem + OFF_BL);
            #pragma unroll
            for (int m = 0; m < 4; m++) {
                dH[tid + m * 256] = srcH[tid + m * 256];
                dL[tid + m * 256] = srcL[tid + m * 256];
            }
        }
        // generate sqrt-gram A tile (128 x 64) split hi/lo
        {
            const float* xjp = x + (size_t)(b * NN + cb * 64 + jj) * 3;
            const float xj0 = __ldg(xjp), xj1 = __ldg(xjp + 1), xj2 = __ldg(xjp + 2);
            unsigned char* aH = smem + OFF_AH;
            unsigned char* aL = smem + OFF_AL;
            #pragma unroll 4
            for (int it = 0; it < 32; it++) {
                const int i = ig * 32 + it;
                float d = xi[i * 3] * xj0 + xi[i * 3 + 1] * xj1 + xi[i * 3 + 2] * xj2;
                float s = fast_sqrt(d);
                unsigned short h = bf16bits(s);
                unsigned short l = bf16bits(s - bf16val(h));
                const unsigned off = i * 128 + ((((jj >> 3) ^ (i & 7))) << 4) + (jj & 7) * 2;
                *(unsigned short*)(aH + off) = h;
                *(unsigned short*)(aL + off) = l;
            }
        }
        __syncthreads();
        mma_k64<128>(acc, sb + OFF_AH, sb + OFF_AL, sb + OFF_BH, sb + OFF_BL, 0, w, lane);
    }

    // ---------------- layer 0 epilogue -> h split; layers 1 & 2 ----------------
    __syncthreads();
    epi_split(acc, smem + 0, smem + 32768, b1s, w, lane);

    #pragma unroll
    for (int cb2 = 0; cb2 < 2; cb2++) {
        __syncthreads();
        const float4* srcH = (const float4*)(gW1_hi + cb2 * 16384);
        const float4* srcL = (const float4*)(gW1_lo + cb2 * 16384);
        float4* dH = (float4*)(smem + OFF_WH);
        float4* dL = (float4*)(smem + OFF_WL);
        #pragma unroll
        for (int m = 0; m < 4; m++) {
            dH[tid + m * 256] = srcH[tid + m * 256];
            dL[tid + m * 256] = srcL[tid + m * 256];
        }
        __syncthreads();
        mma_k64<256>(acc, sb + 0, sb + 32768, sb + OFF_WH, sb + OFF_WL, cb2 * 64, w, lane);
    }

    __syncthreads();
    epi_split(acc, smem + 0, smem + 32768, b2s, w, lane);

    #pragma unroll
    for (int cb2 = 0; cb2 < 2; cb2++) {
        __syncthreads();
        const float4* srcH = (const float4*)(gW2_hi + cb2 * 16384);
        const float4* srcL = (const float4*)(gW2_lo + cb2 * 16384);
        float4* dH = (float4*)(smem + OFF_WH);
        float4* dL = (float4*)(smem + OFF_WL);
        #pragma unroll
        for (int m = 0; m < 4; m++) {
            dH[tid + m * 256] = srcH[tid + m * 256];
            dL[tid + m * 256] = srcL[tid + m * 256];
        }
        __syncthreads();
        mma_k64<256>(acc, sb + 0, sb + 32768, sb + OFF_WH, sb + OFF_WL, cb2 * 64, w, lane);
    }

    // ---------------- final contraction: out[b,c,d] += sum_i fk[i,c] * x[i,d] / N ------
    {
        const int cp = lane & 3, rg = lane >> 2;
        const int r1 = w * 16 + rg, r2 = r1 + 8;
        const float x10 = xi[r1 * 3], x11 = xi[r1 * 3 + 1], x12 = xi[r1 * 3 + 2];
        const float x20 = xi[r2 * 3], x21 = xi[r2 * 3 + 1], x22 = xi[r2 * 3 + 2];
        #pragma unroll
        for (int nf = 0; nf < 16; nf++) {
            float s[6];
            s[0] = acc[nf][0] * x10 + acc[nf][2] * x20;
            s[1] = acc[nf][0] * x11 + acc[nf][2] * x21;
            s[2] = acc[nf][0] * x12 + acc[nf][2] * x22;
            s[3] = acc[nf][1] * x10 + acc[nf][3] * x20;
            s[4] = acc[nf][1] * x11 + acc[nf][3] * x21;
            s[5] = acc[nf][1] * x12 + acc[nf][3] * x22;
            #pragma unroll
            for (int q = 0; q < 6; q++) {
                s[q] += __shfl_xor_sync(0xffffffffu, s[q], 4);
                s[q] += __shfl_xor_sync(0xffffffffu, s[q], 8);
                s[q] += __shfl_xor_sync(0xffffffffu, s[q], 16);
            }
            if (lane < 4) {
                const int c = nf * 8 + lane * 2;
                atomicAdd(&oacc[c * 3 + 0], s[0]);
                atomicAdd(&oacc[c * 3 + 1], s[1]);
                atomicAdd(&oacc[c * 3 + 2], s[2]);
                atomicAdd(&oacc[(c + 1) * 3 + 0], s[3]);
                atomicAdd(&oacc[(c + 1) * 3 + 1], s[4]);
                atomicAdd(&oacc[(c + 1) * 3 + 2], s[5]);
            }
        }
    }
    __syncthreads();
    const float inv = 1.0f / (float)NN;
    for (int t = tid; t < 384; t += 256)
        atomicAdd(out + (size_t)b * 384 + t, oacc[t] * inv);
}

// ---------------------------------------------------------------------------
extern "C" void kernel_launch(void* const* d_in, const int* in_sizes, int n_in,
                              void* d_out, int out_size) {
    const float* x  = (const float*)d_in[0];
    const float* u  = (const float*)d_in[1];
    const float* W0 = (const float*)d_in[2];
    const float* b0 = (const float*)d_in[3];
    const float* W1 = (const float*)d_in[4];
    const float* b1 = (const float*)d_in[5];
    const float* W2 = (const float*)d_in[6];
    const float* b2 = (const float*)d_in[7];
    float* out = (float*)d_out;

    cudaFuncSetAttribute(k_main, cudaFuncAttributeMaxDynamicSharedMemorySize, SMEM_BYTES);

    k_zero<<<12, 1024>>>(out);
    k_prep<<<640, 256>>>(W0, W1, W2);
    k_main<<<BB * (NN / 128), 256, SMEM_BYTES>>>(x, u, W0, b0, b1, b2, out);
}

// round 4
// speedup vs baseline: 2.9059x; 1.3073x over previous
#include <cuda_runtime.h>
#include <cuda_fp16.h>

#define BB 32
#define NN 1024
#define GG 8
#define HH 128

// ---- prepped fp16 operand images (single plane), ldmatrix-swizzled k64 chunks ----
// chunk: 64 k-rows x 128 n-cols fp16, 256B rows; 16B col-chunk XOR-swizzled by (k&7).
__device__ __align__(16) unsigned char gBd[16 * 16384];   // W0 rows 9..1032 (dots)
__device__ __align__(16) unsigned char gW1[2 * 16384];
__device__ __align__(16) unsigned char gW2[2 * 16384];

// ---- smem map (bytes) ----
#define OFF_AH   0        // layer0 A hi (128x64 fp16, 128B rows)
#define OFF_AL   16384    // layer0 A lo
#define OFF_B    32768    // layer0/W B chunk (64x128 fp16, 256B rows)  [mainloop]
#define OFF_HH   0        // h hi (128x128 fp16, 256B rows)  [layer phase]
#define OFF_HL   32768    // h lo
#define OFF_W    65536    // W1/W2 chunk
#define OFF_XI   81920    // x rows fp32 [128][3]
#define OFF_NRM  83456
#define OFF_CU   83968
#define OFF_W0N  84480
#define OFF_B1S  84992
#define OFF_B2S  85504
#define OFF_OACC 86016    // fp32 [128][3]
#define SMEM_BYTES 87552

// ---------------- helpers ----------------
__device__ __forceinline__ unsigned smem_u32(const void* p) {
    unsigned a;
    asm("{ .reg .u64 t; cvta.to.shared.u64 t, %1; cvt.u32.u64 %0, t; }" : "=r"(a) : "l"(p));
    return a;
}
__device__ __forceinline__ void ldsm_x4(unsigned& r0, unsigned& r1, unsigned& r2, unsigned& r3,
                                        unsigned a) {
    asm volatile("ldmatrix.sync.aligned.m8n8.x4.shared.b16 {%0,%1,%2,%3}, [%4];"
                 : "=r"(r0), "=r"(r1), "=r"(r2), "=r"(r3) : "r"(a));
}
__device__ __forceinline__ void ldsm_x2t(unsigned& r0, unsigned& r1, unsigned a) {
    asm volatile("ldmatrix.sync.aligned.m8n8.x2.trans.shared.b16 {%0,%1}, [%2];"
                 : "=r"(r0), "=r"(r1) : "r"(a));
}
__device__ __forceinline__ void mma16816(float* d, unsigned a0, unsigned a1, unsigned a2,
                                         unsigned a3, unsigned b0, unsigned b1) {
    asm volatile(
        "mma.sync.aligned.m16n8k16.row.col.f32.f16.f16.f32 "
        "{%0,%1,%2,%3}, {%4,%5,%6,%7}, {%8,%9}, {%0,%1,%2,%3};"
        : "+f"(d[0]), "+f"(d[1]), "+f"(d[2]), "+f"(d[3])
        : "r"(a0), "r"(a1), "r"(a2), "r"(a3), "r"(b0), "r"(b1));
}
__device__ __forceinline__ float fast_sqrt(float v) {
    float xh = 0.5f * v;
    int i = __float_as_int(v);
    i = 0x5f3759df - (i >> 1);
    float y = __int_as_float(i);
    y = y * (1.5f - xh * y * y);
    y = y * (1.5f - xh * y * y);
    y = y * (1.5f - xh * y * y);
    return v * y;
}
__device__ __forceinline__ float leaky(float v) { return v > 0.0f ? v : 0.01f * v; }

__device__ __forceinline__ unsigned short h16(float v) {
    __half h = __float2half_rn(v);
    return *(unsigned short*)&h;
}
__device__ __forceinline__ float h16v(unsigned short b) {
    __half h = *(__half*)&b;
    return __half2float(h);
}

// k64 MMA sweep: acc += (Ah + Al) x B  (2 MMAs per fragment).
// RSTRIDE: A row stride bytes (128 layer0, 256 h). kOff: A k offset.
template<int RSTRIDE>
__device__ __forceinline__ void mma_k64(float (&acc)[16][4], unsigned aH, unsigned aL,
                                        unsigned bB, int kOff, int w, int lane) {
    const int L = lane;
    const int i = w * 16 + (L & 15);
    #pragma unroll
    for (int ks = 0; ks < 64; ks += 16) {
        const int kc = ((kOff + ks) >> 3) + (L >> 4);
        const unsigned aoff = i * RSTRIDE + ((kc ^ (i & 7)) << 4);
        unsigned ah0, ah1, ah2, ah3, al0, al1, al2, al3;
        ldsm_x4(ah0, ah1, ah2, ah3, aH + aoff);
        ldsm_x4(al0, al1, al2, al3, aL + aoff);
        const int kk = ks + (L & 15);
        const unsigned bbase = kk * 256;
        const int kx = kk & 7;
        #pragma unroll
        for (int nf = 0; nf < 16; nf++) {
            const unsigned boff = bbase + ((nf ^ kx) << 4);
            unsigned b0, b1;
            ldsm_x2t(b0, b1, bB + boff);
            mma16816(acc[nf], ah0, ah1, ah2, ah3, b0, b1);
            mma16816(acc[nf], al0, al1, al2, al3, b0, b1);
        }
    }
}

// Epilogue: leaky + fp16 hi/lo split into h planes (256B rows), re-init acc with bias.
__device__ __forceinline__ void epi_split(float (&acc)[16][4], unsigned char* dH,
                                          unsigned char* dL, const float* nb, int w, int lane) {
    const int cp = lane & 3, rg = lane >> 2;
    const int r1 = w * 16 + rg, r2 = r1 + 8;
    #pragma unroll
    for (int nf = 0; nf < 16; nf++) {
        const int c = nf * 8 + cp * 2;
        float v0 = leaky(acc[nf][0]), v1 = leaky(acc[nf][1]);
        float v2 = leaky(acc[nf][2]), v3 = leaky(acc[nf][3]);
        unsigned short a0 = h16(v0), a1 = h16(v1), a2 = h16(v2), a3 = h16(v3);
        unsigned short l0 = h16(v0 - h16v(a0)), l1 = h16(v1 - h16v(a1));
        unsigned short l2 = h16(v2 - h16v(a2)), l3 = h16(v3 - h16v(a3));
        const unsigned o1 = r1 * 256 + ((((c >> 3) ^ (r1 & 7))) << 4) + (c & 7) * 2;
        const unsigned o2 = r2 * 256 + ((((c >> 3) ^ (r2 & 7))) << 4) + (c & 7) * 2;
        *(unsigned*)(dH + o1) = (unsigned)a0 | ((unsigned)a1 << 16);
        *(unsigned*)(dL + o1) = (unsigned)l0 | ((unsigned)l1 << 16);
        *(unsigned*)(dH + o2) = (unsigned)a2 | ((unsigned)a3 << 16);
        *(unsigned*)(dL + o2) = (unsigned)l2 | ((unsigned)l3 << 16);
        acc[nf][0] = nb[c]; acc[nf][1] = nb[c + 1];
        acc[nf][2] = nb[c]; acc[nf][3] = nb[c + 1];
    }
}

// ---------------------------------------------------------------------------
// Prep (+ output zero): round weights to fp16 into swizzled chunk images.
__global__ void k_prep(const float* __restrict__ W0, const float* __restrict__ W1,
                       const float* __restrict__ W2, float* __restrict__ out) {
    int idx = blockIdx.x * 256 + threadIdx.x;
    float v; unsigned char* dp;
    int k, n;
    if (idx < 131072) {                   // dots rows of W0
        k = idx >> 7; n = idx & 127;
        v = W0[(9 + k) * HH + n];
        dp = gBd;
    } else if (idx < 147456) {            // W1
        int t = idx - 131072;
        k = t >> 7; n = t & 127;
        v = W1[k * HH + n];
        dp = gW1;
    } else if (idx < 163840) {            // W2
        int t = idx - 147456;
        k = t >> 7; n = t & 127;
        v = W2[k * HH + n];
        dp = gW2;
    } else {
        int t = idx - 163840;
        if (t < BB * HH * 3) out[t] = 0.0f;
        return;
    }
    const int cb = k >> 6, kl = k & 63;
    const unsigned off = cb * 16384 + kl * 256 + ((((n >> 3) ^ (kl & 7))) << 4) + (n & 7) * 2;
    *(unsigned short*)(dp + off) = h16(v);
}

// ---------------------------------------------------------------------------
__global__ void __launch_bounds__(256, 2)
k_main(const float* __restrict__ x, const float* __restrict__ u,
       const float* __restrict__ W0, const float* __restrict__ b0,
       const float* __restrict__ b1, const float* __restrict__ b2,
       float* __restrict__ out)
{
    extern __shared__ __align__(1024) unsigned char smem[];
    const unsigned sb = smem_u32(smem);
    const int tid = threadIdx.x, w = tid >> 5, lane = tid & 31;
    const int b = blockIdx.x >> 3, i0 = (blockIdx.x & 7) * 128;

    float* xi   = (float*)(smem + OFF_XI);
    float* nrm  = (float*)(smem + OFF_NRM);
    float* cu   = (float*)(smem + OFF_CU);
    float* w0n  = (float*)(smem + OFF_W0N);
    float* b1s  = (float*)(smem + OFF_B1S);
    float* b2s  = (float*)(smem + OFF_B2S);
    float* oacc = (float*)(smem + OFF_OACC);

    for (int t = tid; t < 384; t += 256) {
        xi[t] = x[(size_t)(b * NN + i0) * 3 + t];
        oacc[t] = 0.0f;
    }
    if (tid < 128) {
        float s = b0[tid];
        #pragma unroll
        for (int g = 0; g < GG; g++) s += u[b * GG + g] * W0[g * HH + tid];
        cu[tid]  = s;
        w0n[tid] = W0[8 * HH + tid];
        b1s[tid] = b1[tid];
        b2s[tid] = b2[tid];
    }
    __syncthreads();
    if (tid < 128) {
        float a = xi[tid * 3], c = xi[tid * 3 + 1], d = xi[tid * 3 + 2];
        nrm[tid] = fast_sqrt(a * a + c * c + d * d);
    }
    __syncthreads();

    // Accumulators: warp w owns rows [16w, 16w+16), 16 n-fragments of width 8.
    float acc[16][4];
    {
        const int cp = lane & 3, rg = lane >> 2;
        const int r1 = w * 16 + rg, r2 = r1 + 8;
        const float n1 = nrm[r1], n2 = nrm[r2];
        #pragma unroll
        for (int nf = 0; nf < 16; nf++) {
            const int c = nf * 8 + cp * 2;
            acc[nf][0] = cu[c]     + n1 * w0n[c];
            acc[nf][1] = cu[c + 1] + n1 * w0n[c + 1];
            acc[nf][2] = cu[c]     + n2 * w0n[c];
            acc[nf][3] = cu[c + 1] + n2 * w0n[c + 1];
        }
    }

    // ---------------- layer 0 mainloop: 16 chunks of k64 gram columns ----------------
    const int jj = tid & 63, ig = tid >> 6;
    for (int cb = 0; cb < 16; cb++) {
        __syncthreads();
        // stage W0 chunk (16 KB)
        {
            const float4* src = (const float4*)(gBd + cb * 16384);
            float4* dst = (float4*)(smem + OFF_B);
            #pragma unroll
            for (int m = 0; m < 4; m++) dst[tid + m * 256] = src[tid + m * 256];
        }
        // generate sqrt-gram A tile (128 x 64), fp16 hi/lo planes
        {
            const float* xjp = x + (size_t)(b * NN + cb * 64 + jj) * 3;
            const float xj0 = __ldg(xjp), xj1 = __ldg(xjp + 1), xj2 = __ldg(xjp + 2);
            unsigned char* aH = smem + OFF_AH;
            unsigned char* aL = smem + OFF_AL;
            #pragma unroll 4
            for (int it = 0; it < 32; it++) {
                const int i = ig * 32 + it;
                float d = xi[i * 3] * xj0 + xi[i * 3 + 1] * xj1 + xi[i * 3 + 2] * xj2;
                float s = fast_sqrt(d);
                unsigned short h = h16(s);
                unsigned short l = h16(s - h16v(h));
                const unsigned off = i * 128 + ((((jj >> 3) ^ (i & 7))) << 4) + (jj & 7) * 2;
                *(unsigned short*)(aH + off) = h;
                *(unsigned short*)(aL + off) = l;
            }
        }
        __syncthreads();
        mma_k64<128>(acc, sb + OFF_AH, sb + OFF_AL, sb + OFF_B, 0, w, lane);
    }

    // ---------------- layer 0 epilogue -> h planes; layers 1 & 2 ----------------
    __syncthreads();
    epi_split(acc, smem + OFF_HH, smem + OFF_HL, b1s, w, lane);

    #pragma unroll
    for (int cb2 = 0; cb2 < 2; cb2++) {
        __syncthreads();
        const float4* src = (const float4*)(gW1 + cb2 * 16384);
        float4* dst = (float4*)(smem + OFF_W);
        #pragma unroll
        for (int m = 0; m < 4; m++) dst[tid + m * 256] = src[tid + m * 256];
        __syncthreads();
        mma_k64<256>(acc, sb + OFF_HH, sb + OFF_HL, sb + OFF_W, cb2 * 64, w, lane);
    }

    __syncthreads();
    epi_split(acc, smem + OFF_HH, smem + OFF_HL, b2s, w, lane);

    #pragma unroll
    for (int cb2 = 0; cb2 < 2; cb2++) {
        __syncthreads();
        const float4* src = (const float4*)(gW2 + cb2 * 16384);
        float4* dst = (float4*)(smem + OFF_W);
        #pragma unroll
        for (int m = 0; m < 4; m++) dst[tid + m * 256] = src[tid + m * 256];
        __syncthreads();
        mma_k64<256>(acc, sb + OFF_HH, sb + OFF_HL, sb + OFF_W, cb2 * 64, w, lane);
    }

    // ---------------- final contraction: out[b,c,d] += sum_i fk[i,c] * x[i,d] / N ------
    {
        const int rg = lane >> 2;
        const int r1 = w * 16 + rg, r2 = r1 + 8;
        const float x10 = xi[r1 * 3], x11 = xi[r1 * 3 + 1], x12 = xi[r1 * 3 + 2];
        const float x20 = xi[r2 * 3], x21 = xi[r2 * 3 + 1], x22 = xi[r2 * 3 + 2];
        #pragma unroll
        for (int nf = 0; nf < 16; nf++) {
            float s[6];
            s[0] = acc[nf][0] * x10 + acc[nf][2] * x20;
            s[1] = acc[nf][0] * x11 + acc[nf][2] * x21;
            s[2] = acc[nf][0] * x12 + acc[nf][2] * x22;
            s[3] = acc[nf][1] * x10 + acc[nf][3] * x20;
            s[4] = acc[nf][1] * x11 + acc[nf][3] * x21;
            s[5] = acc[nf][1] * x12 + acc[nf][3] * x22;
            #pragma unroll
            for (int q = 0; q < 6; q++) {
                s[q] += __shfl_xor_sync(0xffffffffu, s[q], 4);
                s[q] += __shfl_xor_sync(0xffffffffu, s[q], 8);
                s[q] += __shfl_xor_sync(0xffffffffu, s[q], 16);
            }
            if (lane < 4) {
                const int c = nf * 8 + lane * 2;
                atomicAdd(&oacc[c * 3 + 0], s[0]);
                atomicAdd(&oacc[c * 3 + 1], s[1]);
                atomicAdd(&oacc[c * 3 + 2], s[2]);
                atomicAdd(&oacc[(c + 1) * 3 + 0], s[3]);
                atomicAdd(&oacc[(c + 1) * 3 + 1], s[4]);
                atomicAdd(&oacc[(c + 1) * 3 + 2], s[5]);
            }
        }
    }
    __syncthreads();
    const float inv = 1.0f / (float)NN;
    for (int t = tid; t < 384; t += 256)
        atomicAdd(out + (size_t)b * 384 + t, oacc[t] * inv);
}

// ---------------------------------------------------------------------------
extern "C" void kernel_launch(void* const* d_in, const int* in_sizes, int n_in,
                              void* d_out, int out_size) {
    const float* x  = (const float*)d_in[0];
    const float* u  = (const float*)d_in[1];
    const float* W0 = (const float*)d_in[2];
    const float* b0 = (const float*)d_in[3];
    const float* W1 = (const float*)d_in[4];
    const float* b1 = (const float*)d_in[5];
    const float* W2 = (const float*)d_in[6];
    const float* b2 = (const float*)d_in[7];
    float* out = (float*)d_out;

    cudaFuncSetAttribute(k_main, cudaFuncAttributeMaxDynamicSharedMemorySize, SMEM_BYTES);

    k_prep<<<688, 256>>>(W0, W1, W2, out);
    k_main<<<BB * (NN / 128), 256, SMEM_BYTES>>>(x, u, W0, b0, b1, b2, out);
}

// round 5
// speedup vs baseline: 2.9944x; 1.0305x over previous
#include <cuda_runtime.h>
#include <cuda_fp16.h>

#define BB 32
#define NN 1024
#define GG 8
#define HH 128

// ---- prepped fp16 operand images (single plane), ldmatrix-swizzled k64 chunks ----
// chunk: 64 k-rows x 128 n-cols fp16, 256B rows; 16B col-chunk XOR-swizzled by (k&7).
__device__ __align__(16) unsigned char gBd[16 * 16384];   // W0 rows 9..1032 (dots)
__device__ __align__(16) unsigned char gW1[2 * 16384];
__device__ __align__(16) unsigned char gW2[2 * 16384];

// ---- smem map (bytes) ----
#define OFF_AH   0        // layer0 A hi (128x64 fp16, 128B rows)
#define OFF_AL   16384    // layer0 A lo
#define OFF_B    32768    // layer0/W B chunk (64x128 fp16, 256B rows)  [mainloop]
#define OFF_HH   0        // h hi (128x128 fp16, 256B rows)  [layer phase]
#define OFF_HL   32768    // h lo
#define OFF_W    65536    // W1/W2 chunk
#define OFF_XI   81920    // x rows fp32 [128][3]
#define OFF_NRM  83456
#define OFF_CU   83968
#define OFF_W0N  84480
#define OFF_B1S  84992
#define OFF_B2S  85504
#define OFF_OACC 86016    // fp32 [128][3]
#define SMEM_BYTES 87552

// ---------------- helpers ----------------
__device__ __forceinline__ unsigned smem_u32(const void* p) {
    unsigned a;
    asm("{ .reg .u64 t; cvta.to.shared.u64 t, %1; cvt.u32.u64 %0, t; }" : "=r"(a) : "l"(p));
    return a;
}
__device__ __forceinline__ void ldsm_x4(unsigned& r0, unsigned& r1, unsigned& r2, unsigned& r3,
                                        unsigned a) {
    asm volatile("ldmatrix.sync.aligned.m8n8.x4.shared.b16 {%0,%1,%2,%3}, [%4];"
                 : "=r"(r0), "=r"(r1), "=r"(r2), "=r"(r3) : "r"(a));
}
__device__ __forceinline__ void ldsm_x4t(unsigned& r0, unsigned& r1, unsigned& r2, unsigned& r3,
                                         unsigned a) {
    asm volatile("ldmatrix.sync.aligned.m8n8.x4.trans.shared.b16 {%0,%1,%2,%3}, [%4];"
                 : "=r"(r0), "=r"(r1), "=r"(r2), "=r"(r3) : "r"(a));
}
__device__ __forceinline__ void mma16816(float* d, unsigned a0, unsigned a1, unsigned a2,
                                         unsigned a3, unsigned b0, unsigned b1) {
    asm volatile(
        "mma.sync.aligned.m16n8k16.row.col.f32.f16.f16.f32 "
        "{%0,%1,%2,%3}, {%4,%5,%6,%7}, {%8,%9}, {%0,%1,%2,%3};"
        : "+f"(d[0]), "+f"(d[1]), "+f"(d[2]), "+f"(d[3])
        : "r"(a0), "r"(a1), "r"(a2), "r"(a3), "r"(b0), "r"(b1));
}
__device__ __forceinline__ float fast_sqrt(float v) {
    float xh = 0.5f * v;
    int i = __float_as_int(v);
    i = 0x5f3759df - (i >> 1);
    float y = __int_as_float(i);
    y = y * (1.5f - xh * y * y);
    y = y * (1.5f - xh * y * y);
    y = y * (1.5f - xh * y * y);
    return v * y;
}
__device__ __forceinline__ float leaky(float v) { return v > 0.0f ? v : 0.01f * v; }

__device__ __forceinline__ unsigned short h16(float v) {
    __half h = __float2half_rn(v);
    return *(unsigned short*)&h;
}
__device__ __forceinline__ float h16v(unsigned short b) {
    __half h = *(__half*)&b;
    return __half2float(h);
}

// k64 MMA sweep: acc += (Ah + Al) x B.
// Per ks: load A hi/lo, then for each half (8 nf): batch-load 8 B fragments
// (x4.trans, 2 nf per ldsm), issue 8 independent hi-MMAs, then 8 lo-MMAs
// (RAW distance 8 -> HMMA latency hidden at 4 warps/SMSP).
template<int RSTRIDE>
__device__ __forceinline__ void mma_k64(float (&acc)[16][4], unsigned aH, unsigned aL,
                                        unsigned bB, int kOff, int w, int lane) {
    const int i = w * 16 + (lane & 15);
    const unsigned arow = i * RSTRIDE;
    const int ax = i & 7;
    const int kkl = lane & 15;          // k-row within 16-slab (B addressing)
    const int kx  = lane & 7;           // B swizzle selector
    const int nfs = lane >> 4;          // 0/1: which nf of the x4t pair
    #pragma unroll
    for (int ks = 0; ks < 64; ks += 16) {
        const int kc = ((kOff + ks) >> 3) + (lane >> 4);
        const unsigned aoff = arow + ((unsigned)(kc ^ ax) << 4);
        unsigned ah0, ah1, ah2, ah3, al0, al1, al2, al3;
        ldsm_x4(ah0, ah1, ah2, ah3, aH + aoff);
        ldsm_x4(al0, al1, al2, al3, aL + aoff);
        const unsigned bbase = (unsigned)(ks + kkl) * 256;
        #pragma unroll
        for (int h = 0; h < 2; h++) {
            unsigned bb[16];
            #pragma unroll
            for (int p = 0; p < 4; p++) {
                const int nf = h * 8 + p * 2 + nfs;
                const unsigned boff = bbase + ((unsigned)(nf ^ kx) << 4);
                ldsm_x4t(bb[p * 4 + 0], bb[p * 4 + 1], bb[p * 4 + 2], bb[p * 4 + 3],
                         bB + boff);
            }
            #pragma unroll
            for (int p = 0; p < 4; p++) {
                mma16816(acc[h * 8 + p * 2 + 0], ah0, ah1, ah2, ah3, bb[p * 4 + 0], bb[p * 4 + 1]);
                mma16816(acc[h * 8 + p * 2 + 1], ah0, ah1, ah2, ah3, bb[p * 4 + 2], bb[p * 4 + 3]);
            }
            #pragma unroll
            for (int p = 0; p < 4; p++) {
                mma16816(acc[h * 8 + p * 2 + 0], al0, al1, al2, al3, bb[p * 4 + 0], bb[p * 4 + 1]);
                mma16816(acc[h * 8 + p * 2 + 1], al0, al1, al2, al3, bb[p * 4 + 2], bb[p * 4 + 3]);
            }
        }
    }
}

// Epilogue: leaky + fp16 hi/lo split into h planes (256B rows), re-init acc with bias.
__device__ __forceinline__ void epi_split(float (&acc)[16][4], unsigned char* dH,
                                          unsigned char* dL, const float* nb, int w, int lane) {
    const int cp = lane & 3, rg = lane >> 2;
    const int r1 = w * 16 + rg, r2 = r1 + 8;
    #pragma unroll
    for (int nf = 0; nf < 16; nf++) {
        const int c = nf * 8 + cp * 2;
        float v0 = leaky(acc[nf][0]), v1 = leaky(acc[nf][1]);
        float v2 = leaky(acc[nf][2]), v3 = leaky(acc[nf][3]);
        unsigned short a0 = h16(v0), a1 = h16(v1), a2 = h16(v2), a3 = h16(v3);
        unsigned short l0 = h16(v0 - h16v(a0)), l1 = h16(v1 - h16v(a1));
        unsigned short l2 = h16(v2 - h16v(a2)), l3 = h16(v3 - h16v(a3));
        const unsigned o1 = r1 * 256 + ((((c >> 3) ^ (r1 & 7))) << 4) + (c & 7) * 2;
        const unsigned o2 = r2 * 256 + ((((c >> 3) ^ (r2 & 7))) << 4) + (c & 7) * 2;
        *(unsigned*)(dH + o1) = (unsigned)a0 | ((unsigned)a1 << 16);
        *(unsigned*)(dL + o1) = (unsigned)l0 | ((unsigned)l1 << 16);
        *(unsigned*)(dH + o2) = (unsigned)a2 | ((unsigned)a3 << 16);
        *(unsigned*)(dL + o2) = (unsigned)l2 | ((unsigned)l3 << 16);
        acc[nf][0] = nb[c]; acc[nf][1] = nb[c + 1];
        acc[nf][2] = nb[c]; acc[nf][3] = nb[c + 1];
    }
}

// ---------------------------------------------------------------------------
// Prep (+ output zero): round weights to fp16 into swizzled chunk images.
__global__ void k_prep(const float* __restrict__ W0, const float* __restrict__ W1,
                       const float* __restrict__ W2, float* __restrict__ out) {
    int idx = blockIdx.x * 256 + threadIdx.x;
    float v; unsigned char* dp;
    int k, n;
    if (idx < 131072) {                   // dots rows of W0
        k = idx >> 7; n = idx & 127;
        v = W0[(9 + k) * HH + n];
        dp = gBd;
    } else if (idx < 147456) {            // W1
        int t = idx - 131072;
        k = t >> 7; n = t & 127;
        v = W1[k * HH + n];
        dp = gW1;
    } else if (idx < 163840) {            // W2
        int t = idx - 147456;
        k = t >> 7; n = t & 127;
        v = W2[k * HH + n];
        dp = gW2;
    } else {
        int t = idx - 163840;
        if (t < BB * HH * 3) out[t] = 0.0f;
        return;
    }
    const int cb = k >> 6, kl = k & 63;
    const unsigned off = cb * 16384 + kl * 256 + ((((n >> 3) ^ (kl & 7))) << 4) + (n & 7) * 2;
    *(unsigned short*)(dp + off) = h16(v);
}

// ---------------------------------------------------------------------------
__global__ void __launch_bounds__(256, 2)
k_main(const float* __restrict__ x, const float* __restrict__ u,
       const float* __restrict__ W0, const float* __restrict__ b0,
       const float* __restrict__ b1, const float* __restrict__ b2,
       float* __restrict__ out)
{
    extern __shared__ __align__(1024) unsigned char smem[];
    const unsigned sb = smem_u32(smem);
    const int tid = threadIdx.x, w = tid >> 5, lane = tid & 31;
    const int b = blockIdx.x >> 3, i0 = (blockIdx.x & 7) * 128;

    float* xi   = (float*)(smem + OFF_XI);
    float* nrm  = (float*)(smem + OFF_NRM);
    float* cu   = (float*)(smem + OFF_CU);
    float* w0n  = (float*)(smem + OFF_W0N);
    float* b1s  = (float*)(smem + OFF_B1S);
    float* b2s  = (float*)(smem + OFF_B2S);
    float* oacc = (float*)(smem + OFF_OACC);

    for (int t = tid; t < 384; t += 256) {
        xi[t] = x[(size_t)(b * NN + i0) * 3 + t];
        oacc[t] = 0.0f;
    }
    if (tid < 128) {
        float s = b0[tid];
        #pragma unroll
        for (int g = 0; g < GG; g++) s += u[b * GG + g] * W0[g * HH + tid];
        cu[tid]  = s;
        w0n[tid] = W0[8 * HH + tid];
        b1s[tid] = b1[tid];
        b2s[tid] = b2[tid];
    }
    __syncthreads();
    if (tid < 128) {
        float a = xi[tid * 3], c = xi[tid * 3 + 1], d = xi[tid * 3 + 2];
        nrm[tid] = fast_sqrt(a * a + c * c + d * d);
    }
    __syncthreads();

    // Accumulators: warp w owns rows [16w, 16w+16), 16 n-fragments of width 8.
    float acc[16][4];
    {
        const int cp = lane & 3, rg = lane >> 2;
        const int r1 = w * 16 + rg, r2 = r1 + 8;
        const float n1 = nrm[r1], n2 = nrm[r2];
        #pragma unroll
        for (int nf = 0; nf < 16; nf++) {
            const int c = nf * 8 + cp * 2;
            acc[nf][0] = cu[c]     + n1 * w0n[c];
            acc[nf][1] = cu[c + 1] + n1 * w0n[c + 1];
            acc[nf][2] = cu[c]     + n2 * w0n[c];
            acc[nf][3] = cu[c + 1] + n2 * w0n[c + 1];
        }
    }

    // ---------------- layer 0 mainloop: 16 chunks of k64 gram columns ----------------
    const int jj = tid & 63, ig = tid >> 6;
    for (int cb = 0; cb < 16; cb++) {
        __syncthreads();
        // stage W0 chunk (16 KB)
        {
            const float4* src = (const float4*)(gBd + cb * 16384);
            float4* dst = (float4*)(smem + OFF_B);
            #pragma unroll
            for (int m = 0; m < 4; m++) dst[tid + m * 256] = src[tid + m * 256];
        }
        // generate sqrt-gram A tile (128 x 64), fp16 hi/lo planes
        {
            const float* xjp = x + (size_t)(b * NN + cb * 64 + jj) * 3;
            const float xj0 = __ldg(xjp), xj1 = __ldg(xjp + 1), xj2 = __ldg(xjp + 2);
            unsigned char* aH = smem + OFF_AH;
            unsigned char* aL = smem + OFF_AL;
            #pragma unroll 4
            for (int it = 0; it < 32; it++) {
                const int i = ig * 32 + it;
                float d = xi[i * 3] * xj0 + xi[i * 3 + 1] * xj1 + xi[i * 3 + 2] * xj2;
                float s = fast_sqrt(d);
                unsigned short h = h16(s);
                unsigned short l = h16(s - h16v(h));
                const unsigned off = i * 128 + ((((jj >> 3) ^ (i & 7))) << 4) + (jj & 7) * 2;
                *(unsigned short*)(aH + off) = h;
                *(unsigned short*)(aL + off) = l;
            }
        }
        __syncthreads();
        mma_k64<128>(acc, sb + OFF_AH, sb + OFF_AL, sb + OFF_B, 0, w, lane);
    }

    // ---------------- layer 0 epilogue -> h planes; layers 1 & 2 ----------------
    __syncthreads();
    epi_split(acc, smem + OFF_HH, smem + OFF_HL, b1s, w, lane);

    #pragma unroll
    for (int cb2 = 0; cb2 < 2; cb2++) {
        __syncthreads();
        const float4* src = (const float4*)(gW1 + cb2 * 16384);
        float4* dst = (float4*)(smem + OFF_W);
        #pragma unroll
        for (int m = 0; m < 4; m++) dst[tid + m * 256] = src[tid + m * 256];
        __syncthreads();
        mma_k64<256>(acc, sb + OFF_HH, sb + OFF_HL, sb + OFF_W, cb2 * 64, w, lane);
    }

    __syncthreads();
    epi_split(acc, smem + OFF_HH, smem + OFF_HL, b2s, w, lane);

    #pragma unroll
    for (int cb2 = 0; cb2 < 2; cb2++) {
        __syncthreads();
        const float4* src = (const float4*)(gW2 + cb2 * 16384);
        float4* dst = (float4*)(smem + OFF_W);
        #pragma unroll
        for (int m = 0; m < 4; m++) dst[tid + m * 256] = src[tid + m * 256];
        __syncthreads();
        mma_k64<256>(acc, sb + OFF_HH, sb + OFF_HL, sb + OFF_W, cb2 * 64, w, lane);
    }

    // ---------------- final contraction: out[b,c,d] += sum_i fk[i,c] * x[i,d] / N ------
    {
        const int rg = lane >> 2;
        const int r1 = w * 16 + rg, r2 = r1 + 8;
        const float x10 = xi[r1 * 3], x11 = xi[r1 * 3 + 1], x12 = xi[r1 * 3 + 2];
        const float x20 = xi[r2 * 3], x21 = xi[r2 * 3 + 1], x22 = xi[r2 * 3 + 2];
        #pragma unroll
        for (int nf = 0; nf < 16; nf++) {
            float s[6];
            s[0] = acc[nf][0] * x10 + acc[nf][2] * x20;
            s[1] = acc[nf][0] * x11 + acc[nf][2] * x21;
            s[2] = acc[nf][0] * x12 + acc[nf][2] * x22;
            s[3] = acc[nf][1] * x10 + acc[nf][3] * x20;
            s[4] = acc[nf][1] * x11 + acc[nf][3] * x21;
            s[5] = acc[nf][1] * x12 + acc[nf][3] * x22;
            #pragma unroll
            for (int q = 0; q < 6; q++) {
                s[q] += __shfl_xor_sync(0xffffffffu, s[q], 4);
                s[q] += __shfl_xor_sync(0xffffffffu, s[q], 8);
                s[q] += __shfl_xor_sync(0xffffffffu, s[q], 16);
            }
            if (lane < 4) {
                const int c = nf * 8 + lane * 2;
                atomicAdd(&oacc[c * 3 + 0], s[0]);
                atomicAdd(&oacc[c * 3 + 1], s[1]);
                atomicAdd(&oacc[c * 3 + 2], s[2]);
                atomicAdd(&oacc[(c + 1) * 3 + 0], s[3]);
                atomicAdd(&oacc[(c + 1) * 3 + 1], s[4]);
                atomicAdd(&oacc[(c + 1) * 3 + 2], s[5]);
            }
        }
    }
    __syncthreads();
    const float inv = 1.0f / (float)NN;
    for (int t = tid; t < 384; t += 256)
        atomicAdd(out + (size_t)b * 384 + t, oacc[t] * inv);
}

// ---------------------------------------------------------------------------
extern "C" void kernel_launch(void* const* d_in, const int* in_sizes, int n_in,
                              void* d_out, int out_size) {
    const float* x  = (const float*)d_in[0];
    const float* u  = (const float*)d_in[1];
    const float* W0 = (const float*)d_in[2];
    const float* b0 = (const float*)d_in[3];
    const float* W1 = (const float*)d_in[4];
    const float* b1 = (const float*)d_in[5];
    const float* W2 = (const float*)d_in[6];
    const float* b2 = (const float*)d_in[7];
    float* out = (float*)d_out;

    cudaFuncSetAttribute(k_main, cudaFuncAttributeMaxDynamicSharedMemorySize, SMEM_BYTES);

    k_prep<<<688, 256>>>(W0, W1, W2, out);
    k_main<<<BB * (NN / 128), 256, SMEM_BYTES>>>(x, u, W0, b0, b1, b2, out);
}

// round 7
// speedup vs baseline: 5.6043x; 1.8716x over previous
#include <cuda_runtime.h>
#include <cuda_fp16.h>

#define BB 32
#define NN 1024
#define GG 8
#define HH 128

// ---- prepped fp16 weight images, ldmatrix-swizzled k64 chunks ----
// chunk: 64 k-rows x 128 n-cols fp16, 256B rows; 16B col-chunk XOR-swizzled by (k&7).
__device__ __align__(16) unsigned char gBd[16 * 16384];   // W0 rows 9..1032 (dots)
__device__ __align__(16) unsigned char gW1[2 * 16384];
__device__ __align__(16) unsigned char gW2[2 * 16384];

// ---- smem map (bytes); A/B (layer0) and H (layer phase) overlap ----
#define OFF_A    0        // layer0 A (128x64 fp16, 128B rows)           [16KB]
#define OFF_B    16384    // layer0 B chunk (64x128 fp16, 256B rows)     [16KB]
#define OFF_H    0        // h plane (128x128 fp16, 256B rows)           [32KB]
#define OFF_W    32768    // W1/W2 chunk                                 [16KB]
#define OFF_XI   49152    // x rows fp32 [128][3]
#define OFF_NRM  50688
#define OFF_CU   51200
#define OFF_W0N  51712
#define OFF_B1S  52224
#define OFF_B2S  52736
#define OFF_OACC 53248    // fp32 [128][3]
#define SMEM_BYTES 54784

// ---------------- helpers ----------------
__device__ __forceinline__ unsigned smem_u32(const void* p) {
    unsigned a;
    asm("{ .reg .u64 t; cvta.to.shared.u64 t, %1; cvt.u32.u64 %0, t; }" : "=r"(a) : "l"(p));
    return a;
}
__device__ __forceinline__ void ldsm_x4(unsigned* r, unsigned a) {
    asm volatile("ldmatrix.sync.aligned.m8n8.x4.shared.b16 {%0,%1,%2,%3}, [%4];"
                 : "=r"(r[0]), "=r"(r[1]), "=r"(r[2]), "=r"(r[3]) : "r"(a));
}
__device__ __forceinline__ void ldsm_x4t(unsigned* r, unsigned a) {
    asm volatile("ldmatrix.sync.aligned.m8n8.x4.trans.shared.b16 {%0,%1,%2,%3}, [%4];"
                 : "=r"(r[0]), "=r"(r[1]), "=r"(r[2]), "=r"(r[3]) : "r"(a));
}
__device__ __forceinline__ void mma16816(float* d, const unsigned* a, unsigned b0, unsigned b1) {
    asm volatile(
        "mma.sync.aligned.m16n8k16.row.col.f32.f16.f16.f32 "
        "{%0,%1,%2,%3}, {%4,%5,%6,%7}, {%8,%9}, {%0,%1,%2,%3};"
        : "+f"(d[0]), "+f"(d[1]), "+f"(d[2]), "+f"(d[3])
        : "r"(a[0]), "r"(a[1]), "r"(a[2]), "r"(a[3]), "r"(b0), "r"(b1));
}
__device__ __forceinline__ void cpa16(unsigned dst, const void* src) {
    asm volatile("cp.async.cg.shared.global [%0], [%1], 16;" :: "r"(dst), "l"(src));
}
__device__ __forceinline__ void cpa_wait_all() {
    asm volatile("cp.async.wait_all;" ::: "memory");
}
__device__ __forceinline__ float asqrt(float v) {   // MUFU.SQRT
    float r;
    asm("sqrt.approx.f32 %0, %1;" : "=f"(r) : "f"(v));
    return r;
}
__device__ __forceinline__ float leaky(float v) { return v > 0.0f ? v : 0.01f * v; }
__device__ __forceinline__ unsigned short h16(float v) {
    __half h = __float2half_rn(v);
    return *(unsigned short*)&h;
}

// k64 MMA sweep (1-term): acc[m*8+nfl] += A x B.
// Warp = (rg, cg): rows rg*32 + m*16, cols cg*64 + nfl*8.
template<int RSTRIDE>
__device__ __forceinline__ void mma_k64(float (&acc)[16][4], unsigned aBase, unsigned bBase,
                                        int kOff, int rg, int cg, int lane) {
    const int il  = lane & 15;
    const int kq  = lane >> 4;
    const int kkl = lane & 15;
    const int kx  = lane & 7;
    const int nfs = lane >> 4;
    #pragma unroll
    for (int ks = 0; ks < 64; ks += 16) {
        const int kc = ((kOff + ks) >> 3) + kq;
        unsigned a[2][4];
        #pragma unroll
        for (int m = 0; m < 2; m++) {
            const int i = rg * 32 + m * 16 + il;
            ldsm_x4(a[m], aBase + i * RSTRIDE + ((unsigned)(kc ^ (i & 7)) << 4));
        }
        const unsigned bbase = (unsigned)(ks + kkl) * 256;
        unsigned bb[16];
        #pragma unroll
        for (int p = 0; p < 4; p++) {
            const int nf = cg * 8 + p * 2 + nfs;
            ldsm_x4t(bb + p * 4, bBase + bbase + ((unsigned)(nf ^ kx) << 4));
        }
        #pragma unroll
        for (int p = 0; p < 4; p++) {
            #pragma unroll
            for (int m = 0; m < 2; m++) {
                mma16816(acc[m * 8 + p * 2 + 0], a[m], bb[p * 4 + 0], bb[p * 4 + 1]);
                mma16816(acc[m * 8 + p * 2 + 1], a[m], bb[p * 4 + 2], bb[p * 4 + 3]);
            }
        }
    }
}

// Epilogue: leaky + fp16 (1-term) into h plane (256B rows), re-init acc with bias.
__device__ __forceinline__ void epi_split(float (&acc)[16][4], unsigned char* dH,
                                          const float* nb, int rg, int cg, int lane) {
    const int cp = lane & 3, r8 = lane >> 2;
    #pragma unroll
    for (int m = 0; m < 2; m++) {
        const int r1 = rg * 32 + m * 16 + r8, r2 = r1 + 8;
        #pragma unroll
        for (int nfl = 0; nfl < 8; nfl++) {
            float* A = acc[m * 8 + nfl];
            const int c = cg * 64 + nfl * 8 + cp * 2;
            unsigned short a0 = h16(leaky(A[0])), a1 = h16(leaky(A[1]));
            unsigned short a2 = h16(leaky(A[2])), a3 = h16(leaky(A[3]));
            const unsigned o1 = r1 * 256 + ((unsigned)(((c >> 3) ^ (r1 & 7))) << 4) + (c & 7) * 2;
            const unsigned o2 = r2 * 256 + ((unsigned)(((c >> 3) ^ (r2 & 7))) << 4) + (c & 7) * 2;
            *(unsigned*)(dH + o1) = (unsigned)a0 | ((unsigned)a1 << 16);
            *(unsigned*)(dH + o2) = (unsigned)a2 | ((unsigned)a3 << 16);
            A[0] = nb[c]; A[1] = nb[c + 1]; A[2] = nb[c]; A[3] = nb[c + 1];
        }
    }
}

// ---------------------------------------------------------------------------
// Prep (+ output zero): round weights to fp16 into swizzled chunk images.
__global__ void k_prep(const float* __restrict__ W0, const float* __restrict__ W1,
                       const float* __restrict__ W2, float* __restrict__ out) {
    int idx = blockIdx.x * 256 + threadIdx.x;
    float v; unsigned char* dp;
    int k, n;
    if (idx < 131072) {                   // dots rows of W0
        k = idx >> 7; n = idx & 127;
        v = W0[(9 + k) * HH + n];
        dp = gBd;
    } else if (idx < 147456) {            // W1
        int t = idx - 131072;
        k = t >> 7; n = t & 127;
        v = W1[k * HH + n];
        dp = gW1;
    } else if (idx < 163840) {            // W2
        int t = idx - 147456;
        k = t >> 7; n = t & 127;
        v = W2[k * HH + n];
        dp = gW2;
    } else {
        int t = idx - 163840;
        if (t < BB * HH * 3) out[t] = 0.0f;
        return;
    }
    const int cb = k >> 6, kl = k & 63;
    const unsigned off = cb * 16384 + kl * 256 + ((((n >> 3) ^ (kl & 7))) << 4) + (n & 7) * 2;
    *(unsigned short*)(dp + off) = h16(v);
}

// ---------------------------------------------------------------------------
__global__ void __launch_bounds__(256, 2)
k_main(const float* __restrict__ x, const float* __restrict__ u,
       const float* __restrict__ W0, const float* __restrict__ b0,
       const float* __restrict__ b1, const float* __restrict__ b2,
       float* __restrict__ out)
{
    extern __shared__ __align__(1024) unsigned char smem[];
    const unsigned sb = smem_u32(smem);
    const int tid = threadIdx.x, w = tid >> 5, lane = tid & 31;
    const int rg = w & 3, cg = w >> 2;
    const int b = blockIdx.x >> 3, i0 = (blockIdx.x & 7) * 128;

    float* xi   = (float*)(smem + OFF_XI);
    float* nrm  = (float*)(smem + OFF_NRM);
    float* cu   = (float*)(smem + OFF_CU);
    float* w0n  = (float*)(smem + OFF_W0N);
    float* b1s  = (float*)(smem + OFF_B1S);
    float* b2s  = (float*)(smem + OFF_B2S);
    float* oacc = (float*)(smem + OFF_OACC);

    for (int t = tid; t < 384; t += 256) {
        xi[t] = x[(size_t)(b * NN + i0) * 3 + t];
        oacc[t] = 0.0f;
    }
    if (tid < 128) {
        float s = b0[tid];
        #pragma unroll
        for (int g = 0; g < GG; g++) s += u[b * GG + g] * W0[g * HH + tid];
        cu[tid]  = s;
        w0n[tid] = W0[8 * HH + tid];
        b1s[tid] = b1[tid];
        b2s[tid] = b2[tid];
    }
    __syncthreads();
    if (tid < 128) {
        float a = xi[tid * 3], c = xi[tid * 3 + 1], d = xi[tid * 3 + 2];
        nrm[tid] = asqrt(a * a + c * c + d * d);
    }
    __syncthreads();

    // acc[m*8+nfl][4]: rows rg*32 + m*16 (+r8/+8), cols cg*64 + nfl*8 (+cp*2)
    float acc[16][4];
    {
        const int cp = lane & 3, r8 = lane >> 2;
        #pragma unroll
        for (int m = 0; m < 2; m++) {
            const int r1 = rg * 32 + m * 16 + r8, r2 = r1 + 8;
            const float n1 = nrm[r1], n2 = nrm[r2];
            #pragma unroll
            for (int nfl = 0; nfl < 8; nfl++) {
                const int c = cg * 64 + nfl * 8 + cp * 2;
                float* A = acc[m * 8 + nfl];
                A[0] = cu[c]     + n1 * w0n[c];
                A[1] = cu[c + 1] + n1 * w0n[c + 1];
                A[2] = cu[c]     + n2 * w0n[c];
                A[3] = cu[c + 1] + n2 * w0n[c + 1];
            }
        }
    }

    // ---------------- layer 0 mainloop: 16 chunks of k64 gram columns ----------------
    const int jj2 = (tid & 31) * 2;   // j pair base 0..62
    const int ig  = tid >> 5;         // row group 0..7 (16 rows each)
    for (int cb = 0; cb < 16; cb++) {
        __syncthreads();
        // stage W0 chunk via cp.async (16 KB)
        {
            const unsigned char* src = gBd + cb * 16384 + tid * 16;
            unsigned dst = sb + OFF_B + tid * 16;
            #pragma unroll
            for (int m = 0; m < 4; m++) cpa16(dst + m * 4096, src + m * 4096);
        }
        // generate sqrt-gram A tile (128 x 64), fp16 1-term, half2 stores
        {
            const float* xjp = x + (size_t)(b * NN + cb * 64 + jj2) * 3;
            const float xa0 = __ldg(xjp),     xa1 = __ldg(xjp + 1), xa2 = __ldg(xjp + 2);
            const float xb0 = __ldg(xjp + 3), xb1 = __ldg(xjp + 4), xb2 = __ldg(xjp + 5);
            unsigned char* aT = smem + OFF_A;
            const unsigned csw = (unsigned)(jj2 >> 3) << 4;   // col chunk base (j pair in same chunk)
            const unsigned cby = (unsigned)(jj2 & 7) * 2;
            #pragma unroll 4
            for (int it = 0; it < 16; it++) {
                const int i = ig * 16 + it;
                const float y0 = xi[i * 3], y1 = xi[i * 3 + 1], y2 = xi[i * 3 + 2];
                float s0 = asqrt(y0 * xa0 + y1 * xa1 + y2 * xa2);
                float s1 = asqrt(y0 * xb0 + y1 * xb1 + y2 * xb2);
                __half2 hv = __floats2half2_rn(s0, s1);
                const unsigned off = i * 128 + (csw ^ ((unsigned)(i & 7) << 4)) + cby;
                *(unsigned*)(aT + off) = *(unsigned*)&hv;
            }
        }
        cpa_wait_all();
        __syncthreads();
        mma_k64<128>(acc, sb + OFF_A, sb + OFF_B, 0, rg, cg, lane);
    }

    // ---------------- layer 0 epilogue -> h plane; layers 1 & 2 ----------------
    __syncthreads();
    epi_split(acc, smem + OFF_H, b1s, rg, cg, lane);

    #pragma unroll
    for (int cb2 = 0; cb2 < 2; cb2++) {
        __syncthreads();
        {
            const unsigned char* src = gW1 + cb2 * 16384 + tid * 16;
            unsigned dst = sb + OFF_W + tid * 16;
            #pragma unroll
            for (int m = 0; m < 4; m++) cpa16(dst + m * 4096, src + m * 4096);
        }
        cpa_wait_all();
        __syncthreads();
        mma_k64<256>(acc, sb + OFF_H, sb + OFF_W, cb2 * 64, rg, cg, lane);
    }

    __syncthreads();
    epi_split(acc, smem + OFF_H, b2s, rg, cg, lane);

    #pragma unroll
    for (int cb2 = 0; cb2 < 2; cb2++) {
        __syncthreads();
        {
            const unsigned char* src = gW2 + cb2 * 16384 + tid * 16;
            unsigned dst = sb + OFF_W + tid * 16;
            #pragma unroll
            for (int m = 0; m < 4; m++) cpa16(dst + m * 4096, src + m * 4096);
        }
        cpa_wait_all();
        __syncthreads();
        mma_k64<256>(acc, sb + OFF_H, sb + OFF_W, cb2 * 64, rg, cg, lane);
    }

    // ---------------- final contraction: out[b,c,d] += sum_i fk[i,c] * x[i,d] / N ------
    {
        const int r8 = lane >> 2;
        #pragma unroll
        for (int m = 0; m < 2; m++) {
            const int r1 = rg * 32 + m * 16 + r8, r2 = r1 + 8;
            const float x10 = xi[r1 * 3], x11 = xi[r1 * 3 + 1], x12 = xi[r1 * 3 + 2];
            const float x20 = xi[r2 * 3], x21 = xi[r2 * 3 + 1], x22 = xi[r2 * 3 + 2];
            #pragma unroll
            for (int nfl = 0; nfl < 8; nfl++) {
                float* A = acc[m * 8 + nfl];
                float s[6];
                s[0] = A[0] * x10 + A[2] * x20;
                s[1] = A[0] * x11 + A[2] * x21;
                s[2] = A[0] * x12 + A[2] * x22;
                s[3] = A[1] * x10 + A[3] * x20;
                s[4] = A[1] * x11 + A[3] * x21;
                s[5] = A[1] * x12 + A[3] * x22;
                #pragma unroll
                for (int q = 0; q < 6; q++) {
                    s[q] += __shfl_xor_sync(0xffffffffu, s[q], 4);
                    s[q] += __shfl_xor_sync(0xffffffffu, s[q], 8);
                    s[q] += __shfl_xor_sync(0xffffffffu, s[q], 16);
                }
                if (lane < 4) {
                    const int c = cg * 64 + nfl * 8 + lane * 2;
                    atomicAdd(&oacc[c * 3 + 0], s[0]);
                    atomicAdd(&oacc[c * 3 + 1], s[1]);
                    atomicAdd(&oacc[c * 3 + 2], s[2]);
                    atomicAdd(&oacc[(c + 1) * 3 + 0], s[3]);
                    atomicAdd(&oacc[(c + 1) * 3 + 1], s[4]);
                    atomicAdd(&oacc[(c + 1) * 3 + 2], s[5]);
                }
            }
        }
    }
    __syncthreads();
    const float inv = 1.0f / (float)NN;
    for (int t = tid; t < 384; t += 256)
        atomicAdd(out + (size_t)b * 384 + t, oacc[t] * inv);
}

// ---------------------------------------------------------------------------
extern "C" void kernel_launch(void* const* d_in, const int* in_sizes, int n_in,
                              void* d_out, int out_size) {
    const float* x  = (const float*)d_in[0];
    const float* u  = (const float*)d_in[1];
    const float* W0 = (const float*)d_in[2];
    const float* b0 = (const float*)d_in[3];
    const float* W1 = (const float*)d_in[4];
    const float* b1 = (const float*)d_in[5];
    const float* W2 = (const float*)d_in[6];
    const float* b2 = (const float*)d_in[7];
    float* out = (float*)d_out;

    cudaFuncSetAttribute(k_main, cudaFuncAttributeMaxDynamicSharedMemorySize, SMEM_BYTES);

    k_prep<<<688, 256>>>(W0, W1, W2, out);
    k_main<<<BB * (NN / 128), 256, SMEM_BYTES>>>(x, u, W0, b0, b1, b2, out);
}